// round 6
// baseline (speedup 1.0000x reference)
#include <cuda_runtime.h>
#include <cuda_bf16.h>
#include <cstdint>

#define NROWS 8192
#define NDIM  128
#define NS    64

static constexpr float EXP_SCALE = 14.4269504088896340736f; // log2(e)/tau

// ---------------- device scratch (fp8 operands) ----------------
__device__ __align__(256) uint8_t g_a [NROWS * NDIM];  // e4m3(n1 * log2(e)/tau)
__device__ __align__(256) uint8_t g_b1[NROWS * NDIM];  // e4m3(n1)
__device__ __align__(256) uint8_t g_b2[NROWS * NDIM];  // e4m3(n2)
__device__ float g_d12[NROWS];
__device__ float g_d11[NROWS];
__device__ float g_adv[NROWS];
__device__ float g_rowsum[2][NROWS];

// ---------------- helpers ----------------
__device__ __forceinline__ uint32_t smem_u32(const void* p) {
    uint32_t a;
    asm("{ .reg .u64 t; cvta.to.shared.u64 t, %1; cvt.u32.u64 %0, t; }" : "=r"(a) : "l"(p));
    return a;
}
__device__ __forceinline__ float warp_sum(float v) {
#pragma unroll
    for (int o = 16; o > 0; o >>= 1) v += __shfl_xor_sync(0xFFFFFFFFu, v, o);
    return v;
}
__device__ __forceinline__ float ex2f(float x) {
    float y; asm("ex2.approx.f32 %0, %1;" : "=f"(y) : "f"(x)); return y;
}
__device__ __forceinline__ void ldsm_x4(uint32_t& r0, uint32_t& r1, uint32_t& r2, uint32_t& r3,
                                        uint32_t addr) {
    asm volatile("ldmatrix.sync.aligned.m8n8.x4.shared.b16 {%0,%1,%2,%3}, [%4];"
                 : "=r"(r0), "=r"(r1), "=r"(r2), "=r"(r3) : "r"(addr));
}
__device__ __forceinline__ void mma_fp8(float& c0, float& c1, float& c2, float& c3,
                                        uint32_t a0, uint32_t a1, uint32_t a2, uint32_t a3,
                                        uint32_t b0, uint32_t b1) {
    asm volatile(
        "mma.sync.aligned.m16n8k32.row.col.f32.e4m3.e4m3.f32 "
        "{%0,%1,%2,%3},{%4,%5,%6,%7},{%8,%9},{%0,%1,%2,%3};"
        : "+f"(c0), "+f"(c1), "+f"(c2), "+f"(c3)
        : "r"(a0), "r"(a1), "r"(a2), "r"(a3), "r"(b0), "r"(b1));
}
// pack 4 fp32 -> 4 e4m3 bytes (order consistent across A and B => dot invariant)
__device__ __forceinline__ uint32_t pack_e4m3_4(float v0, float v1, float v2, float v3) {
    uint16_t lo, hi;
    asm("cvt.rn.satfinite.e4m3x2.f32 %0, %1, %2;" : "=h"(lo) : "f"(v1), "f"(v0));
    asm("cvt.rn.satfinite.e4m3x2.f32 %0, %1, %2;" : "=h"(hi) : "f"(v3), "f"(v2));
    return (uint32_t)lo | ((uint32_t)hi << 16);
}
// exp2(x), exp2(y) via f16x2 MUFU, accumulate both into s (fp32)
__device__ __forceinline__ void exp2_acc(float& s, float x, float y) {
    uint32_t h, e;
    asm("cvt.rn.f16x2.f32 %0, %1, %2;" : "=r"(h) : "f"(x), "f"(y));
    asm("ex2.approx.f16x2 %0, %1;" : "=r"(e) : "r"(h));
    float fx, fy;
    asm("{.reg .b16 l,u; mov.b32 {l,u}, %2; cvt.f32.f16 %0, l; cvt.f32.f16 %1, u;}"
        : "=f"(fx), "=f"(fy) : "r"(e));
    s += fx + fy;
}

// fp8 tile: 128 rows x 128 bytes, 8 chunks(16B)/row, chunk swizzle c ^= (row&7)
__device__ __forceinline__ uint32_t tile_addr(uint32_t base, uint32_t row, uint32_t chunk) {
    return base + row * 128u + ((chunk ^ (row & 7u)) << 4);
}
__device__ __forceinline__ void load_tile_async(uint32_t dst, const uint8_t* src) {
    int t = threadIdx.x;
#pragma unroll
    for (int j = 0; j < 4; ++j) {
        uint32_t q = (uint32_t)t + 256u * j;   // 1024 16B chunks
        uint32_t r = q >> 3, c = q & 7u;
        uint32_t d = tile_addr(dst, r, c);
        const uint8_t* g = src + ((size_t)r << 7) + ((size_t)c << 4);
        asm volatile("cp.async.cg.shared.global [%0], [%1], 16;" :: "r"(d), "l"(g) : "memory");
    }
    asm volatile("cp.async.commit_group;" ::: "memory");
}
#define CP_WAIT(n) asm volatile("cp.async.wait_group %0;" :: "n"(n) : "memory")

static constexpr int TILE_BYTES = 16384;
static constexpr int SMEM_A_OFF = 0;
static constexpr int SMEM_B_OFF = TILE_BYTES;
static constexpr int SMEM_DYN   = TILE_BYTES * 4;   // A + 3 B stages = 64KB

// ---------------- kernel A: normalize + diagonals + adversarial ----------------
__global__ void __launch_bounds__(256) prep_kernel(const float* __restrict__ z1,
                                                   const float* __restrict__ z2,
                                                   const float* __restrict__ cpre,
                                                   const float* __restrict__ lab) {
    int w = threadIdx.x >> 5, lane = threadIdx.x & 31;
    int row = blockIdx.x * 8 + w;
    float4 a = ((const float4*)(z1 + (size_t)row * NDIM))[lane];
    float4 b = ((const float4*)(z2 + (size_t)row * NDIM))[lane];
    float ss1 = warp_sum(a.x * a.x + a.y * a.y + a.z * a.z + a.w * a.w);
    float ss2 = warp_sum(b.x * b.x + b.y * b.y + b.z * b.z + b.w * b.w);
    float inv1 = 1.f / fmaxf(sqrtf(ss1), 1e-8f);
    float inv2 = 1.f / fmaxf(sqrtf(ss2), 1e-8f);
    float4 n1 = make_float4(a.x * inv1, a.y * inv1, a.z * inv1, a.w * inv1);
    float4 n2 = make_float4(b.x * inv2, b.y * inv2, b.z * inv2, b.w * inv2);
    float d12 = warp_sum(n1.x * n2.x + n1.y * n2.y + n1.z * n2.z + n1.w * n2.w);
    float d11 = warp_sum(n1.x * n1.x + n1.y * n1.y + n1.z * n1.z + n1.w * n1.w);

    ((uint32_t*)(g_a  + (size_t)row * NDIM))[lane] =
        pack_e4m3_4(n1.x * EXP_SCALE, n1.y * EXP_SCALE, n1.z * EXP_SCALE, n1.w * EXP_SCALE);
    ((uint32_t*)(g_b1 + (size_t)row * NDIM))[lane] = pack_e4m3_4(n1.x, n1.y, n1.z, n1.w);
    ((uint32_t*)(g_b2 + (size_t)row * NDIM))[lane] = pack_e4m3_4(n2.x, n2.y, n2.z, n2.w);
    if (lane == 0) { g_d12[row] = d12; g_d11[row] = d11; }

    // adversarial: picked = c_norm[row, argmax(label_row)] (first-max tie-break)
    float2 cc = ((const float2*)(cpre + (size_t)row * NS))[lane];
    float2 ll = ((const float2*)(lab + (size_t)row * NS))[lane];
    float csum = warp_sum(cc.x * cc.x + cc.y * cc.y);
    float bv = ll.x; int bi = lane * 2; float bc = cc.x;
    if (ll.y > bv) { bv = ll.y; bi = lane * 2 + 1; bc = cc.y; }
#pragma unroll
    for (int o = 16; o > 0; o >>= 1) {
        float ov = __shfl_xor_sync(0xFFFFFFFFu, bv, o);
        int   oi = __shfl_xor_sync(0xFFFFFFFFu, bi, o);
        float oc = __shfl_xor_sync(0xFFFFFFFFu, bc, o);
        if (ov > bv || (ov == bv && oi < bi)) { bv = ov; bi = oi; bc = oc; }
    }
    if (lane == 0) {
        float picked = bc / fmaxf(sqrtf(csum), 1e-12f);
        g_adv[row] = -logf(1e-12f + 1.f - picked);
    }
}

// ---------------- sim kernel tile step ----------------
// One 128x128 B tile: 4 k32-steps of fp8 mma into `cur`, with the f16x2-exp
// epilogue of the PREVIOUS tile (`prv`) interleaved for pipe overlap.
__device__ __forceinline__ void tile_step(int t, uint32_t base, const uint8_t* Bsrc,
                                          const uint32_t (&af)[2][4][4],
                                          uint32_t rB0, uint32_t gB,
                                          float (&cur)[2][8][4], float (&prv)[2][8][4],
                                          bool do_epi, float (&s)[2][2]) {
    if (t < 63) { CP_WAIT(1); } else { CP_WAIT(0); }
    __syncthreads();
    if (t + 2 < 64)
        load_tile_async(base + SMEM_B_OFF + (uint32_t)((t + 2) % 3) * TILE_BYTES,
                        Bsrc + (size_t)(t + 2) * 128 * NDIM);
    const uint32_t bstage = base + SMEM_B_OFF + (uint32_t)(t % 3) * TILE_BYTES;
#pragma unroll
    for (int ks = 0; ks < 4; ++ks) {
        uint32_t bf[4][4];
#pragma unroll
        for (int nb = 0; nb < 4; ++nb) {
            uint32_t addr = tile_addr(bstage, rB0 + nb * 16u, 2u * ks + gB);
            ldsm_x4(bf[nb][0], bf[nb][1], bf[nb][2], bf[nb][3], addr);
        }
#pragma unroll
        for (int mb = 0; mb < 2; ++mb)
#pragma unroll
            for (int nb = 0; nb < 4; ++nb) {
                mma_fp8(cur[mb][nb * 2][0], cur[mb][nb * 2][1],
                        cur[mb][nb * 2][2], cur[mb][nb * 2][3],
                        af[mb][ks][0], af[mb][ks][1], af[mb][ks][2], af[mb][ks][3],
                        bf[nb][0], bf[nb][1]);
                mma_fp8(cur[mb][nb * 2 + 1][0], cur[mb][nb * 2 + 1][1],
                        cur[mb][nb * 2 + 1][2], cur[mb][nb * 2 + 1][3],
                        af[mb][ks][0], af[mb][ks][1], af[mb][ks][2], af[mb][ks][3],
                        bf[nb][2], bf[nb][3]);
            }
        if (do_epi) {
#pragma unroll
            for (int mb = 0; mb < 2; ++mb)
#pragma unroll
                for (int j = 0; j < 2; ++j) {
                    int nt = 2 * ks + j;
                    exp2_acc(s[mb][0], prv[mb][nt][0], prv[mb][nt][1]);
                    exp2_acc(s[mb][1], prv[mb][nt][2], prv[mb][nt][3]);
                    prv[mb][nt][0] = 0.f; prv[mb][nt][1] = 0.f;
                    prv[mb][nt][2] = 0.f; prv[mb][nt][3] = 0.f;
                }
        }
    }
}

// ---------------- kernel B: fused sim-GEMM (fp8) + exp row-sums ----------------
// grid (64, 2): x = 128-row A tile, y = matrix (0: vs n2 -> S12, 1: vs n1 -> S11)
// 8 warps: 4 M-slabs (32 rows) x 2 N-slabs (64 cols). A fragments persistent.
__global__ void __launch_bounds__(256, 1) sim_rowsum_kernel() {
    extern __shared__ char smem_raw[];
    const uint32_t base = smem_u32(smem_raw);
    const int tid  = threadIdx.x;
    const int wid  = tid >> 5;
    const int lane = tid & 31;
    const int tile_i = blockIdx.x;
    const int mat    = blockIdx.y;
    const uint8_t* Asrc = g_a + (size_t)tile_i * 128 * NDIM;
    const uint8_t* Bsrc = mat ? g_b1 : g_b2;

    const int m_base = (wid & 3) * 32;
    const int jslab  = wid >> 2;

    load_tile_async(base + SMEM_A_OFF, Asrc);
    load_tile_async(base + SMEM_B_OFF, Bsrc);
    load_tile_async(base + SMEM_B_OFF + TILE_BYTES, Bsrc + 128 * NDIM);

    CP_WAIT(2);
    __syncthreads();

    // persistent A fragments: af[mblk][kstep][4]
    uint32_t af[2][4][4];
    {
        uint32_t rA = (uint32_t)(m_base + (lane & 15));
        uint32_t gA = (uint32_t)(lane >> 4);
#pragma unroll
        for (int mb = 0; mb < 2; ++mb)
#pragma unroll
            for (int ks = 0; ks < 4; ++ks) {
                uint32_t addr = tile_addr(base + SMEM_A_OFF, rA + mb * 16u, 2u * ks + gA);
                ldsm_x4(af[mb][ks][0], af[mb][ks][1], af[mb][ks][2], af[mb][ks][3], addr);
            }
    }

    const uint32_t rB0 = (uint32_t)(jslab * 64 + (lane & 7) + ((lane >> 4) << 3));
    const uint32_t gB  = (uint32_t)((lane >> 3) & 1);

    float cA[2][8][4], cB[2][8][4];
#pragma unroll
    for (int mb = 0; mb < 2; ++mb)
#pragma unroll
        for (int n = 0; n < 8; ++n)
#pragma unroll
            for (int q = 0; q < 4; ++q) { cA[mb][n][q] = 0.f; cB[mb][n][q] = 0.f; }
    float s[2][2] = {{0.f, 0.f}, {0.f, 0.f}};

    for (int tp = 0; tp < 32; ++tp) {
        tile_step(2 * tp,     base, Bsrc, af, rB0, gB, cA, cB, tp > 0, s);
        tile_step(2 * tp + 1, base, Bsrc, af, rB0, gB, cB, cA, true,  s);
    }
    // final epilogue: tile 63 accumulated into cB
#pragma unroll
    for (int mb = 0; mb < 2; ++mb)
#pragma unroll
        for (int nt = 0; nt < 8; ++nt) {
            exp2_acc(s[mb][0], cB[mb][nt][0], cB[mb][nt][1]);
            exp2_acc(s[mb][1], cB[mb][nt][2], cB[mb][nt][3]);
        }

    // reduce across the 4 lanes sharing a row
#pragma unroll
    for (int o = 1; o <= 2; o <<= 1) {
        s[0][0] += __shfl_xor_sync(0xFFFFFFFFu, s[0][0], o);
        s[0][1] += __shfl_xor_sync(0xFFFFFFFFu, s[0][1], o);
        s[1][0] += __shfl_xor_sync(0xFFFFFFFFu, s[1][0], o);
        s[1][1] += __shfl_xor_sync(0xFFFFFFFFu, s[1][1], o);
    }
    __syncthreads();
    float* buf = (float*)smem_raw;   // buf[2][128]
    if ((lane & 3) == 0) {
        int r = m_base + (lane >> 2);
        buf[jslab * 128 + r]      = s[0][0];
        buf[jslab * 128 + r + 8]  = s[0][1];
        buf[jslab * 128 + r + 16] = s[1][0];
        buf[jslab * 128 + r + 24] = s[1][1];
    }
    __syncthreads();
    if (tid < 128)
        g_rowsum[mat][tile_i * 128 + tid] = buf[tid] + buf[tid + 128];
}

// ---------------- kernel C: final reduction ----------------
__global__ void __launch_bounds__(256) finish_kernel(float* __restrict__ out) {
    __shared__ float sc[256], sa[256];
    int tid = threadIdx.x;
    float c = 0.f, a = 0.f;
    for (int r = tid; r < NROWS; r += 256) {
        float num  = ex2f(EXP_SCALE * g_d12[r]);
        float diag = ex2f(EXP_SCALE * g_d11[r]);
        float den  = g_rowsum[0][r] + g_rowsum[1][r] - diag;
        c -= logf(1e-12f + num / den);
        a += g_adv[r];
    }
    sc[tid] = c; sa[tid] = a;
    __syncthreads();
    for (int st = 128; st > 0; st >>= 1) {
        if (tid < st) { sc[tid] += sc[tid + st]; sa[tid] += sa[tid + st]; }
        __syncthreads();
    }
    if (tid == 0)
        out[0] = sc[0] / (8192.0f * 16383.0f) + sa[0];
}

extern "C" void kernel_launch(void* const* d_in, const int* in_sizes, int n_in,
                              void* d_out, int out_size) {
    const float* z1  = (const float*)d_in[0];
    const float* z2  = (const float*)d_in[1];
    const float* c   = (const float*)d_in[2];
    const float* lab = (const float*)d_in[3];
    cudaFuncSetAttribute(sim_rowsum_kernel,
                         cudaFuncAttributeMaxDynamicSharedMemorySize, SMEM_DYN);
    prep_kernel<<<NROWS / 8, 256>>>(z1, z2, c, lab);
    dim3 g(64, 2);
    sim_rowsum_kernel<<<g, 256, SMEM_DYN>>>();
    finish_kernel<<<1, 256>>>((float*)d_out);
}

// round 7
// speedup vs baseline: 1.0594x; 1.0594x over previous
#include <cuda_runtime.h>
#include <cuda_bf16.h>
#include <cstdint>

#define NROWS 8192
#define NDIM  128
#define NS    64

static constexpr float EXP_SCALE = 14.4269504088896340736f; // log2(e)/tau

// ---------------- device scratch (fp8 operands) ----------------
__device__ __align__(256) uint8_t g_a [NROWS * NDIM];  // e4m3(n1 * log2(e)/tau)
__device__ __align__(256) uint8_t g_b1[NROWS * NDIM];  // e4m3(n1)
__device__ __align__(256) uint8_t g_b2[NROWS * NDIM];  // e4m3(n2)
__device__ float g_d12[NROWS];
__device__ float g_d11[NROWS];
__device__ float g_adv[NROWS];
__device__ float g_rowsum[2][NROWS];

// ---------------- helpers ----------------
__device__ __forceinline__ uint32_t smem_u32(const void* p) {
    uint32_t a;
    asm("{ .reg .u64 t; cvta.to.shared.u64 t, %1; cvt.u32.u64 %0, t; }" : "=r"(a) : "l"(p));
    return a;
}
__device__ __forceinline__ float warp_sum(float v) {
#pragma unroll
    for (int o = 16; o > 0; o >>= 1) v += __shfl_xor_sync(0xFFFFFFFFu, v, o);
    return v;
}
__device__ __forceinline__ float ex2f(float x) {
    float y; asm("ex2.approx.f32 %0, %1;" : "=f"(y) : "f"(x)); return y;
}
__device__ __forceinline__ void ldsm_x4(uint32_t& r0, uint32_t& r1, uint32_t& r2, uint32_t& r3,
                                        uint32_t addr) {
    asm volatile("ldmatrix.sync.aligned.m8n8.x4.shared.b16 {%0,%1,%2,%3}, [%4];"
                 : "=r"(r0), "=r"(r1), "=r"(r2), "=r"(r3) : "r"(addr));
}
__device__ __forceinline__ void mma_fp8(float& c0, float& c1, float& c2, float& c3,
                                        uint32_t a0, uint32_t a1, uint32_t a2, uint32_t a3,
                                        uint32_t b0, uint32_t b1) {
    asm volatile(
        "mma.sync.aligned.m16n8k32.row.col.f32.e4m3.e4m3.f32 "
        "{%0,%1,%2,%3},{%4,%5,%6,%7},{%8,%9},{%0,%1,%2,%3};"
        : "+f"(c0), "+f"(c1), "+f"(c2), "+f"(c3)
        : "r"(a0), "r"(a1), "r"(a2), "r"(a3), "r"(b0), "r"(b1));
}
// pack 4 fp32 -> 4 e4m3 bytes (order consistent across A and B => dot invariant)
__device__ __forceinline__ uint32_t pack_e4m3_4(float v0, float v1, float v2, float v3) {
    uint16_t lo, hi;
    asm("cvt.rn.satfinite.e4m3x2.f32 %0, %1, %2;" : "=h"(lo) : "f"(v1), "f"(v0));
    asm("cvt.rn.satfinite.e4m3x2.f32 %0, %1, %2;" : "=h"(hi) : "f"(v3), "f"(v2));
    return (uint32_t)lo | ((uint32_t)hi << 16);
}
// exp2(x), exp2(y) via one f16x2 MUFU op, accumulate both into s (fp32)
__device__ __forceinline__ void exp2_acc(float& s, float x, float y) {
    uint32_t h, e;
    asm("cvt.rn.f16x2.f32 %0, %1, %2;" : "=r"(h) : "f"(x), "f"(y));
    asm("ex2.approx.f16x2 %0, %1;" : "=r"(e) : "r"(h));
    float fx, fy;
    asm("{.reg .b16 l,u; mov.b32 {l,u}, %2; cvt.f32.f16 %0, l; cvt.f32.f16 %1, u;}"
        : "=f"(fx), "=f"(fy) : "r"(e));
    s += fx + fy;
}

// fp8 tile: 128 rows x 128 bytes, 8 chunks(16B)/row, chunk swizzle c ^= (row&7)
__device__ __forceinline__ uint32_t tile_addr(uint32_t base, uint32_t row, uint32_t chunk) {
    return base + row * 128u + ((chunk ^ (row & 7u)) << 4);
}
__device__ __forceinline__ void load_tile_async(uint32_t dst, const uint8_t* src) {
    int t = threadIdx.x;
#pragma unroll
    for (int j = 0; j < 4; ++j) {
        uint32_t q = (uint32_t)t + 256u * j;   // 1024 16B chunks
        uint32_t r = q >> 3, c = q & 7u;
        uint32_t d = tile_addr(dst, r, c);
        const uint8_t* g = src + ((size_t)r << 7) + ((size_t)c << 4);
        asm volatile("cp.async.cg.shared.global [%0], [%1], 16;" :: "r"(d), "l"(g) : "memory");
    }
    asm volatile("cp.async.commit_group;" ::: "memory");
}
#define CP_WAIT(n) asm volatile("cp.async.wait_group %0;" :: "n"(n) : "memory")

static constexpr int TILE_BYTES = 16384;
static constexpr int SMEM_A_OFF = 0;
static constexpr int SMEM_B_OFF = TILE_BYTES;
static constexpr int SMEM_DYN   = TILE_BYTES * 4;   // A + 3 B stages = 64KB

// ---------------- kernel A: normalize + diagonals + adversarial ----------------
__global__ void __launch_bounds__(256) prep_kernel(const float* __restrict__ z1,
                                                   const float* __restrict__ z2,
                                                   const float* __restrict__ cpre,
                                                   const float* __restrict__ lab) {
    int w = threadIdx.x >> 5, lane = threadIdx.x & 31;
    int row = blockIdx.x * 8 + w;
    float4 a = ((const float4*)(z1 + (size_t)row * NDIM))[lane];
    float4 b = ((const float4*)(z2 + (size_t)row * NDIM))[lane];
    float ss1 = warp_sum(a.x * a.x + a.y * a.y + a.z * a.z + a.w * a.w);
    float ss2 = warp_sum(b.x * b.x + b.y * b.y + b.z * b.z + b.w * b.w);
    float inv1 = 1.f / fmaxf(sqrtf(ss1), 1e-8f);
    float inv2 = 1.f / fmaxf(sqrtf(ss2), 1e-8f);
    float4 n1 = make_float4(a.x * inv1, a.y * inv1, a.z * inv1, a.w * inv1);
    float4 n2 = make_float4(b.x * inv2, b.y * inv2, b.z * inv2, b.w * inv2);
    float d12 = warp_sum(n1.x * n2.x + n1.y * n2.y + n1.z * n2.z + n1.w * n2.w);
    float d11 = warp_sum(n1.x * n1.x + n1.y * n1.y + n1.z * n1.z + n1.w * n1.w);

    ((uint32_t*)(g_a  + (size_t)row * NDIM))[lane] =
        pack_e4m3_4(n1.x * EXP_SCALE, n1.y * EXP_SCALE, n1.z * EXP_SCALE, n1.w * EXP_SCALE);
    ((uint32_t*)(g_b1 + (size_t)row * NDIM))[lane] = pack_e4m3_4(n1.x, n1.y, n1.z, n1.w);
    ((uint32_t*)(g_b2 + (size_t)row * NDIM))[lane] = pack_e4m3_4(n2.x, n2.y, n2.z, n2.w);
    if (lane == 0) { g_d12[row] = d12; g_d11[row] = d11; }

    // adversarial: picked = c_norm[row, argmax(label_row)] (first-max tie-break)
    float2 cc = ((const float2*)(cpre + (size_t)row * NS))[lane];
    float2 ll = ((const float2*)(lab + (size_t)row * NS))[lane];
    float csum = warp_sum(cc.x * cc.x + cc.y * cc.y);
    float bv = ll.x; int bi = lane * 2; float bc = cc.x;
    if (ll.y > bv) { bv = ll.y; bi = lane * 2 + 1; bc = cc.y; }
#pragma unroll
    for (int o = 16; o > 0; o >>= 1) {
        float ov = __shfl_xor_sync(0xFFFFFFFFu, bv, o);
        int   oi = __shfl_xor_sync(0xFFFFFFFFu, bi, o);
        float oc = __shfl_xor_sync(0xFFFFFFFFu, bc, o);
        if (ov > bv || (ov == bv && oi < bi)) { bv = ov; bi = oi; bc = oc; }
    }
    if (lane == 0) {
        float picked = bc / fmaxf(sqrtf(csum), 1e-12f);
        g_adv[row] = -logf(1e-12f + 1.f - picked);
    }
}

// ---------------- kernel B: fused sim-GEMM (fp8) + exp row-sums ----------------
// grid (64, 2): x = 128-row A tile, y = matrix (0: vs n2 -> S12, 1: vs n1 -> S11)
// 8 warps: 4 M-slabs (32 rows) x 2 N-slabs (64 cols). A fragments persistent.
// Single accumulator bank; epilogue after the mma loop (R5 control flow).
__global__ void __launch_bounds__(256, 1) sim_rowsum_kernel() {
    extern __shared__ char smem_raw[];
    const uint32_t base = smem_u32(smem_raw);
    const int tid  = threadIdx.x;
    const int wid  = tid >> 5;
    const int lane = tid & 31;
    const int tile_i = blockIdx.x;
    const int mat    = blockIdx.y;
    const uint8_t* Asrc = g_a + (size_t)tile_i * 128 * NDIM;
    const uint8_t* Bsrc = mat ? g_b1 : g_b2;

    const int m_base = (wid & 3) * 32;
    const int jslab  = wid >> 2;

    load_tile_async(base + SMEM_A_OFF, Asrc);
    load_tile_async(base + SMEM_B_OFF, Bsrc);
    load_tile_async(base + SMEM_B_OFF + TILE_BYTES, Bsrc + 128 * NDIM);

    CP_WAIT(2);
    __syncthreads();

    // persistent A fragments: af[mblk][kstep][4]
    uint32_t af[2][4][4];
    {
        uint32_t rA = (uint32_t)(m_base + (lane & 15));
        uint32_t gA = (uint32_t)(lane >> 4);
#pragma unroll
        for (int mb = 0; mb < 2; ++mb)
#pragma unroll
            for (int ks = 0; ks < 4; ++ks) {
                uint32_t addr = tile_addr(base + SMEM_A_OFF, rA + mb * 16u, 2u * ks + gA);
                ldsm_x4(af[mb][ks][0], af[mb][ks][1], af[mb][ks][2], af[mb][ks][3], addr);
            }
    }

    const uint32_t rB0 = (uint32_t)(jslab * 64 + (lane & 7) + ((lane >> 4) << 3));
    const uint32_t gB  = (uint32_t)((lane >> 3) & 1);

    float s00 = 0.f, s01 = 0.f, s10 = 0.f, s11 = 0.f;

    for (int t = 0; t < 64; ++t) {
        if (t < 63) { CP_WAIT(1); } else { CP_WAIT(0); }
        __syncthreads();
        if (t + 2 < 64)
            load_tile_async(base + SMEM_B_OFF + (uint32_t)((t + 2) % 3) * TILE_BYTES,
                            Bsrc + (size_t)(t + 2) * 128 * NDIM);

        const uint32_t bstage = base + SMEM_B_OFF + (uint32_t)(t % 3) * TILE_BYTES;
        float c[2][8][4];
#pragma unroll
        for (int mb = 0; mb < 2; ++mb)
#pragma unroll
            for (int n = 0; n < 8; ++n)
#pragma unroll
                for (int q = 0; q < 4; ++q) c[mb][n][q] = 0.f;

#pragma unroll
        for (int ks = 0; ks < 4; ++ks) {
            uint32_t bf[4][4];
#pragma unroll
            for (int nb = 0; nb < 4; ++nb) {
                uint32_t addr = tile_addr(bstage, rB0 + nb * 16u, 2u * ks + gB);
                ldsm_x4(bf[nb][0], bf[nb][1], bf[nb][2], bf[nb][3], addr);
            }
#pragma unroll
            for (int mb = 0; mb < 2; ++mb)
#pragma unroll
                for (int nb = 0; nb < 4; ++nb) {
                    mma_fp8(c[mb][nb * 2][0], c[mb][nb * 2][1],
                            c[mb][nb * 2][2], c[mb][nb * 2][3],
                            af[mb][ks][0], af[mb][ks][1], af[mb][ks][2], af[mb][ks][3],
                            bf[nb][0], bf[nb][1]);
                    mma_fp8(c[mb][nb * 2 + 1][0], c[mb][nb * 2 + 1][1],
                            c[mb][nb * 2 + 1][2], c[mb][nb * 2 + 1][3],
                            af[mb][ks][0], af[mb][ks][1], af[mb][ks][2], af[mb][ks][3],
                            bf[nb][2], bf[nb][3]);
                }
        }
        // epilogue: f16x2 exp2 + row accumulation
#pragma unroll
        for (int n = 0; n < 8; ++n) {
            exp2_acc(s00, c[0][n][0], c[0][n][1]);
            exp2_acc(s01, c[0][n][2], c[0][n][3]);
            exp2_acc(s10, c[1][n][0], c[1][n][1]);
            exp2_acc(s11, c[1][n][2], c[1][n][3]);
        }
    }

    // reduce across the 4 lanes sharing a row
#pragma unroll
    for (int o = 1; o <= 2; o <<= 1) {
        s00 += __shfl_xor_sync(0xFFFFFFFFu, s00, o);
        s01 += __shfl_xor_sync(0xFFFFFFFFu, s01, o);
        s10 += __shfl_xor_sync(0xFFFFFFFFu, s10, o);
        s11 += __shfl_xor_sync(0xFFFFFFFFu, s11, o);
    }
    __syncthreads();
    float* buf = (float*)smem_raw;   // buf[2][128]
    if ((lane & 3) == 0) {
        int r = m_base + (lane >> 2);
        buf[jslab * 128 + r]      = s00;
        buf[jslab * 128 + r + 8]  = s01;
        buf[jslab * 128 + r + 16] = s10;
        buf[jslab * 128 + r + 24] = s11;
    }
    __syncthreads();
    if (tid < 128)
        g_rowsum[mat][tile_i * 128 + tid] = buf[tid] + buf[tid + 128];
}

// ---------------- kernel C: final reduction ----------------
__global__ void __launch_bounds__(256) finish_kernel(float* __restrict__ out) {
    __shared__ float sc[256], sa[256];
    int tid = threadIdx.x;
    float c = 0.f, a = 0.f;
    for (int r = tid; r < NROWS; r += 256) {
        float num  = ex2f(EXP_SCALE * g_d12[r]);
        float diag = ex2f(EXP_SCALE * g_d11[r]);
        float den  = g_rowsum[0][r] + g_rowsum[1][r] - diag;
        c -= logf(1e-12f + num / den);
        a += g_adv[r];
    }
    sc[tid] = c; sa[tid] = a;
    __syncthreads();
    for (int st = 128; st > 0; st >>= 1) {
        if (tid < st) { sc[tid] += sc[tid + st]; sa[tid] += sa[tid + st]; }
        __syncthreads();
    }
    if (tid == 0)
        out[0] = sc[0] / (8192.0f * 16383.0f) + sa[0];
}

extern "C" void kernel_launch(void* const* d_in, const int* in_sizes, int n_in,
                              void* d_out, int out_size) {
    const float* z1  = (const float*)d_in[0];
    const float* z2  = (const float*)d_in[1];
    const float* c   = (const float*)d_in[2];
    const float* lab = (const float*)d_in[3];
    cudaFuncSetAttribute(sim_rowsum_kernel,
                         cudaFuncAttributeMaxDynamicSharedMemorySize, SMEM_DYN);
    prep_kernel<<<NROWS / 8, 256>>>(z1, z2, c, lab);
    dim3 g(64, 2);
    sim_rowsum_kernel<<<g, 256, SMEM_DYN>>>();
    finish_kernel<<<1, 256>>>((float*)d_out);
}

// round 8
// speedup vs baseline: 1.3296x; 1.2551x over previous
#include <cuda_runtime.h>
#include <cuda_bf16.h>
#include <cstdint>

#define NROWS 8192
#define NDIM  128
#define NS    64

static constexpr float EXP_SCALE = 14.4269504088896340736f; // log2(e)/tau

// ---------------- device scratch (bf16 operands) ----------------
__device__ __align__(256) __nv_bfloat16 g_a [NROWS * NDIM];  // n1 * log2(e)/tau
__device__ __align__(256) __nv_bfloat16 g_b1[NROWS * NDIM];  // n1
__device__ __align__(256) __nv_bfloat16 g_b2[NROWS * NDIM];  // n2
__device__ float g_d12[NROWS];
__device__ float g_d11[NROWS];
__device__ float g_adv[NROWS];
__device__ float g_rowsum[2][NROWS];

// ---------------- helpers ----------------
__device__ __forceinline__ uint32_t smem_u32(const void* p) {
    uint32_t a;
    asm("{ .reg .u64 t; cvta.to.shared.u64 t, %1; cvt.u32.u64 %0, t; }" : "=r"(a) : "l"(p));
    return a;
}
__device__ __forceinline__ float warp_sum(float v) {
#pragma unroll
    for (int o = 16; o > 0; o >>= 1) v += __shfl_xor_sync(0xFFFFFFFFu, v, o);
    return v;
}
__device__ __forceinline__ float ex2f(float x) {
    float y; asm("ex2.approx.f32 %0, %1;" : "=f"(y) : "f"(x)); return y;
}
__device__ __forceinline__ void ldsm_x4(uint32_t& r0, uint32_t& r1, uint32_t& r2, uint32_t& r3,
                                        uint32_t addr) {
    asm volatile("ldmatrix.sync.aligned.m8n8.x4.shared.b16 {%0,%1,%2,%3}, [%4];"
                 : "=r"(r0), "=r"(r1), "=r"(r2), "=r"(r3) : "r"(addr));
}
__device__ __forceinline__ void mma_bf16(float& c0, float& c1, float& c2, float& c3,
                                         uint32_t a0, uint32_t a1, uint32_t a2, uint32_t a3,
                                         uint32_t b0, uint32_t b1) {
    asm volatile(
        "mma.sync.aligned.m16n8k16.row.col.f32.bf16.bf16.f32 "
        "{%0,%1,%2,%3},{%4,%5,%6,%7},{%8,%9},{%0,%1,%2,%3};"
        : "+f"(c0), "+f"(c1), "+f"(c2), "+f"(c3)
        : "r"(a0), "r"(a1), "r"(a2), "r"(a3), "r"(b0), "r"(b1));
}
__device__ __forceinline__ void mbar_init(uint32_t a, uint32_t c) {
    asm volatile("mbarrier.init.shared.b64 [%0], %1;" :: "r"(a), "r"(c) : "memory");
}
// wait passes iff the phase with the given parity has completed
__device__ __forceinline__ void mbar_wait(uint32_t a, uint32_t par) {
    asm volatile(
        "{\n\t.reg .pred P1;\n\t"
        "W_%=:\n\t"
        "mbarrier.try_wait.parity.acquire.cta.shared::cta.b64 P1, [%0], %1, 0x989680;\n\t"
        "@P1 bra.uni D_%=;\n\t"
        "bra.uni W_%=;\n\t"
        "D_%=:\n\t}"
        :: "r"(a), "r"(par) : "memory");
}
__device__ __forceinline__ void mbar_arrive(uint32_t a) {
    asm volatile("mbarrier.arrive.shared.b64 _, [%0];" :: "r"(a) : "memory");
}

// bf16 tile: 128 rows x 256B, 16 chunks(16B)/row, chunk swizzle c ^= (row&7)
__device__ __forceinline__ uint32_t tile_addr(uint32_t base, uint32_t row, uint32_t chunk) {
    return base + row * 256u + ((chunk ^ (row & 7u)) << 4);
}

static constexpr int TILE_BYTES  = 32768;
static constexpr int SMEM_A_OFF  = 0;
static constexpr int SMEM_STG_OFF = TILE_BYTES;                    // 4 stages
static constexpr int SMEM_BAR_OFF = SMEM_STG_OFF + 4 * TILE_BYTES; // 163840
static constexpr int SMEM_DYN    = SMEM_BAR_OFF + 128;
// full[s] = BAR + s*16 ; empty[s] = BAR + s*16 + 8

// ---------------- kernel A: normalize + diagonals + adversarial ----------------
__global__ void __launch_bounds__(256) prep_kernel(const float* __restrict__ z1,
                                                   const float* __restrict__ z2,
                                                   const float* __restrict__ cpre,
                                                   const float* __restrict__ lab) {
    int w = threadIdx.x >> 5, lane = threadIdx.x & 31;
    int row = blockIdx.x * 8 + w;
    float4 a = ((const float4*)(z1 + (size_t)row * NDIM))[lane];
    float4 b = ((const float4*)(z2 + (size_t)row * NDIM))[lane];
    float ss1 = warp_sum(a.x * a.x + a.y * a.y + a.z * a.z + a.w * a.w);
    float ss2 = warp_sum(b.x * b.x + b.y * b.y + b.z * b.z + b.w * b.w);
    float inv1 = 1.f / fmaxf(sqrtf(ss1), 1e-8f);
    float inv2 = 1.f / fmaxf(sqrtf(ss2), 1e-8f);
    float4 n1 = make_float4(a.x * inv1, a.y * inv1, a.z * inv1, a.w * inv1);
    float4 n2 = make_float4(b.x * inv2, b.y * inv2, b.z * inv2, b.w * inv2);
    float d12 = warp_sum(n1.x * n2.x + n1.y * n2.y + n1.z * n2.z + n1.w * n2.w);
    float d11 = warp_sum(n1.x * n1.x + n1.y * n1.y + n1.z * n1.z + n1.w * n1.w);

    __nv_bfloat162* pa = (__nv_bfloat162*)(g_a + (size_t)row * NDIM) + lane * 2;
    pa[0] = __floats2bfloat162_rn(n1.x * EXP_SCALE, n1.y * EXP_SCALE);
    pa[1] = __floats2bfloat162_rn(n1.z * EXP_SCALE, n1.w * EXP_SCALE);
    __nv_bfloat162* p1 = (__nv_bfloat162*)(g_b1 + (size_t)row * NDIM) + lane * 2;
    p1[0] = __floats2bfloat162_rn(n1.x, n1.y);
    p1[1] = __floats2bfloat162_rn(n1.z, n1.w);
    __nv_bfloat162* p2 = (__nv_bfloat162*)(g_b2 + (size_t)row * NDIM) + lane * 2;
    p2[0] = __floats2bfloat162_rn(n2.x, n2.y);
    p2[1] = __floats2bfloat162_rn(n2.z, n2.w);
    if (lane == 0) { g_d12[row] = d12; g_d11[row] = d11; }

    // adversarial: picked = c_norm[row, argmax(label_row)] (first-max tie-break)
    float2 cc = ((const float2*)(cpre + (size_t)row * NS))[lane];
    float2 ll = ((const float2*)(lab + (size_t)row * NS))[lane];
    float csum = warp_sum(cc.x * cc.x + cc.y * cc.y);
    float bv = ll.x; int bi = lane * 2; float bc = cc.x;
    if (ll.y > bv) { bv = ll.y; bi = lane * 2 + 1; bc = cc.y; }
#pragma unroll
    for (int o = 16; o > 0; o >>= 1) {
        float ov = __shfl_xor_sync(0xFFFFFFFFu, bv, o);
        int   oi = __shfl_xor_sync(0xFFFFFFFFu, bi, o);
        float oc = __shfl_xor_sync(0xFFFFFFFFu, bc, o);
        if (ov > bv || (ov == bv && oi < bi)) { bv = ov; bi = oi; bc = oc; }
    }
    if (lane == 0) {
        float picked = bc / fmaxf(sqrtf(csum), 1e-12f);
        g_adv[row] = -logf(1e-12f + 1.f - picked);
    }
}

// ---------------- kernel B: warp-specialized fused sim-GEMM + exp row-sums ----
// grid (64, 2). 10 warps: wid 0-7 compute (4 M-slabs x 2 N-slabs), wid 8-9 producers.
// 4-stage cp.async ring, full/empty mbarriers, NO block sync in the main loop.
__global__ void __launch_bounds__(320, 1) sim_rowsum_kernel() {
    extern __shared__ char smem_raw[];
    const uint32_t base = smem_u32(smem_raw);
    const int tid  = threadIdx.x;
    const int wid  = tid >> 5;
    const int lane = tid & 31;
    const int tile_i = blockIdx.x;
    const int mat    = blockIdx.y;
    const __nv_bfloat16* Asrc = g_a + (size_t)tile_i * 128 * NDIM;
    const __nv_bfloat16* Bsrc = mat ? g_b1 : g_b2;

    if (tid == 0) {
#pragma unroll
        for (int s = 0; s < 4; ++s) {
            mbar_init(base + SMEM_BAR_OFF + s * 16, 64);      // full: 64 producer threads
            mbar_init(base + SMEM_BAR_OFF + s * 16 + 8, 8);   // empty: 8 compute warps
        }
    }
    __syncthreads();   // barriers visible before any use

    if (wid >= 8) {
        // ---------------- producers ----------------
        const int pid = tid - 256;                 // 0..63
        const char* asrc = (const char*)Asrc;
        // A tile (completion signaled implicitly via full[0])
#pragma unroll
        for (int j = 0; j < 32; ++j) {
            uint32_t q = (uint32_t)pid + 64u * j;  // 2048 chunks
            uint32_t r = q >> 4, c = q & 15u;
            uint32_t d = tile_addr(base + SMEM_A_OFF, r, c);
            asm volatile("cp.async.cg.shared.global [%0], [%1], 16;"
                         :: "r"(d), "l"(asrc + ((size_t)r << 8) + ((size_t)c << 4)) : "memory");
        }
        for (int t = 0; t < 64; ++t) {
            const int s = t & 3, w = t >> 2;
            mbar_wait(base + SMEM_BAR_OFF + s * 16 + 8, 1u ^ (uint32_t)(w & 1));
            const char* src = (const char*)(Bsrc + (size_t)t * 128 * NDIM);
            const uint32_t stg = base + SMEM_STG_OFF + (uint32_t)s * TILE_BYTES;
#pragma unroll
            for (int j = 0; j < 32; ++j) {
                uint32_t q = (uint32_t)pid + 64u * j;
                uint32_t r = q >> 4, c = q & 15u;
                uint32_t d = tile_addr(stg, r, c);
                asm volatile("cp.async.cg.shared.global [%0], [%1], 16;"
                             :: "r"(d), "l"(src + ((size_t)r << 8) + ((size_t)c << 4)) : "memory");
            }
            asm volatile("cp.async.mbarrier.arrive.noinc.shared::cta.b64 [%0];"
                         :: "r"(base + SMEM_BAR_OFF + s * 16) : "memory");
        }
    }

    float s00 = 0.f, s01 = 0.f, s10 = 0.f, s11 = 0.f;
    const int m_base = (wid & 3) * 32;
    const int jslab  = wid >> 2;

    if (wid < 8) {
        // ---------------- consumers ----------------
        // wait full[0] (implies A tile complete), load persistent A fragments
        mbar_wait(base + SMEM_BAR_OFF + 0, 0);
        uint32_t af[2][8][4];
        {
            uint32_t rA = (uint32_t)(m_base + (lane & 15));
            uint32_t gA = (uint32_t)(lane >> 4);
#pragma unroll
            for (int mb = 0; mb < 2; ++mb)
#pragma unroll
                for (int k = 0; k < 8; ++k) {
                    uint32_t addr = tile_addr(base + SMEM_A_OFF, rA + mb * 16u, 2u * k + gA);
                    ldsm_x4(af[mb][k][0], af[mb][k][1], af[mb][k][2], af[mb][k][3], addr);
                }
        }
        const uint32_t rB0 = (uint32_t)(jslab * 64 + (lane & 7) + ((lane >> 4) << 3));
        const uint32_t gB  = (uint32_t)((lane >> 3) & 1);

        for (int t = 0; t < 64; ++t) {
            const int s = t & 3, w = t >> 2;
            mbar_wait(base + SMEM_BAR_OFF + s * 16, (uint32_t)(w & 1));
            const uint32_t bstage = base + SMEM_STG_OFF + (uint32_t)s * TILE_BYTES;

            float c[2][8][4];
#pragma unroll
            for (int mb = 0; mb < 2; ++mb)
#pragma unroll
                for (int n = 0; n < 8; ++n)
#pragma unroll
                    for (int q = 0; q < 4; ++q) c[mb][n][q] = 0.f;

#pragma unroll
            for (int k = 0; k < 8; ++k) {
                uint32_t bf[4][4];
#pragma unroll
                for (int nb = 0; nb < 4; ++nb) {
                    uint32_t addr = tile_addr(bstage, rB0 + nb * 16u, 2u * k + gB);
                    ldsm_x4(bf[nb][0], bf[nb][1], bf[nb][2], bf[nb][3], addr);
                }
#pragma unroll
                for (int mb = 0; mb < 2; ++mb)
#pragma unroll
                    for (int nb = 0; nb < 4; ++nb) {
                        mma_bf16(c[mb][nb * 2][0], c[mb][nb * 2][1],
                                 c[mb][nb * 2][2], c[mb][nb * 2][3],
                                 af[mb][k][0], af[mb][k][1], af[mb][k][2], af[mb][k][3],
                                 bf[nb][0], bf[nb][1]);
                        mma_bf16(c[mb][nb * 2 + 1][0], c[mb][nb * 2 + 1][1],
                                 c[mb][nb * 2 + 1][2], c[mb][nb * 2 + 1][3],
                                 af[mb][k][0], af[mb][k][1], af[mb][k][2], af[mb][k][3],
                                 bf[nb][2], bf[nb][3]);
                    }
            }
            // all ldsm data consumed -> release the stage before the epilogue
            __syncwarp();
            if (lane == 0) mbar_arrive(base + SMEM_BAR_OFF + s * 16 + 8);

            // epilogue: fp32 exp2 + row accumulation (overlaps producer refill)
#pragma unroll
            for (int n = 0; n < 8; ++n) {
                s00 += ex2f(c[0][n][0]) + ex2f(c[0][n][1]);
                s01 += ex2f(c[0][n][2]) + ex2f(c[0][n][3]);
                s10 += ex2f(c[1][n][0]) + ex2f(c[1][n][1]);
                s11 += ex2f(c[1][n][2]) + ex2f(c[1][n][3]);
            }
        }
        // reduce across the 4 lanes sharing a row
#pragma unroll
        for (int o = 1; o <= 2; o <<= 1) {
            s00 += __shfl_xor_sync(0xFFFFFFFFu, s00, o);
            s01 += __shfl_xor_sync(0xFFFFFFFFu, s01, o);
            s10 += __shfl_xor_sync(0xFFFFFFFFu, s10, o);
            s11 += __shfl_xor_sync(0xFFFFFFFFu, s11, o);
        }
    }

    __syncthreads();                       // all warps done; reuse A smem as buf
    float* buf = (float*)smem_raw;         // buf[2][128]
    if (wid < 8 && (lane & 3) == 0) {
        int r = m_base + (lane >> 2);
        buf[jslab * 128 + r]      = s00;
        buf[jslab * 128 + r + 8]  = s01;
        buf[jslab * 128 + r + 16] = s10;
        buf[jslab * 128 + r + 24] = s11;
    }
    __syncthreads();
    if (tid < 128)
        g_rowsum[mat][tile_i * 128 + tid] = buf[tid] + buf[tid + 128];
}

// ---------------- kernel C: final reduction ----------------
__global__ void __launch_bounds__(256) finish_kernel(float* __restrict__ out) {
    __shared__ float sc[256], sa[256];
    int tid = threadIdx.x;
    float c = 0.f, a = 0.f;
    for (int r = tid; r < NROWS; r += 256) {
        float num  = ex2f(EXP_SCALE * g_d12[r]);
        float diag = ex2f(EXP_SCALE * g_d11[r]);
        float den  = g_rowsum[0][r] + g_rowsum[1][r] - diag;
        c -= logf(1e-12f + num / den);
        a += g_adv[r];
    }
    sc[tid] = c; sa[tid] = a;
    __syncthreads();
    for (int st = 128; st > 0; st >>= 1) {
        if (tid < st) { sc[tid] += sc[tid + st]; sa[tid] += sa[tid + st]; }
        __syncthreads();
    }
    if (tid == 0)
        out[0] = sc[0] / (8192.0f * 16383.0f) + sa[0];
}

extern "C" void kernel_launch(void* const* d_in, const int* in_sizes, int n_in,
                              void* d_out, int out_size) {
    const float* z1  = (const float*)d_in[0];
    const float* z2  = (const float*)d_in[1];
    const float* c   = (const float*)d_in[2];
    const float* lab = (const float*)d_in[3];
    cudaFuncSetAttribute(sim_rowsum_kernel,
                         cudaFuncAttributeMaxDynamicSharedMemorySize, SMEM_DYN);
    prep_kernel<<<NROWS / 8, 256>>>(z1, z2, c, lab);
    dim3 g(64, 2);
    sim_rowsum_kernel<<<g, 256 + 64, SMEM_DYN>>>();
    finish_kernel<<<1, 256>>>((float*)d_out);
}